// round 1
// baseline (speedup 1.0000x reference)
#include <cuda_runtime.h>

// Problem constants
// x:  [512, 2048] f32
// q1: [8192, 2048] int32 (values 0..15), s1/z1: [8192, 16] f32, b1: [8192] f32
// q2: [2048, 8192] int32,                s2/z2: [2048, 64] f32, b2: [2048] f32
// out: [512, 2048] f32

#define B_DIM   512
#define D_IN    2048
#define D_H     8192
#define D_OUT   2048

// Scratch for the hidden activation h = relu(x @ w1^T + b1)  (16 MB)
__device__ float g_h[B_DIM * D_H];

// C[M,N] = A[M,K] @ dequant(Q[N,K])^T + bias, optional ReLU.
// Dequant: w[n,k] = (Q[n,k] - Z[n, k/128]) * S[n, k/128]
template<int BM, int BN, int BK, int TM, int TN, bool RELU>
__global__ void __launch_bounds__(256)
gemm_dq_kernel(const float* __restrict__ A,
               const int*   __restrict__ Q,
               const float* __restrict__ S,
               const float* __restrict__ Z,
               const float* __restrict__ bias,
               float* __restrict__ C,
               int M, int N, int K)
{
    const int n0  = blockIdx.x * BN;
    const int m0  = blockIdx.y * BM;
    const int tid = threadIdx.x;
    const int NG  = K >> 7;   // groups along K

    __shared__ float As[BK][BM];   // transposed: As[k][m]
    __shared__ float Bs[BK][BN];   // transposed: Bs[k][n] (dequantized)

    const int tx = tid % (BN / TN);
    const int ty = tid / (BN / TN);

    float acc[TM][TN];
    #pragma unroll
    for (int i = 0; i < TM; i++)
        #pragma unroll
        for (int j = 0; j < TN; j++) acc[i][j] = 0.0f;

    constexpr int C4 = BK / 4;            // float4 chunks per K-row
    constexpr int LA = BM * C4 / 256;     // A float4 loads per thread
    constexpr int LB = BN * C4 / 256;     // Q int4 loads per thread

    for (int kt = 0; kt < K; kt += BK) {
        const int g = kt >> 7;            // BK=16 never spans a 128-group

        #pragma unroll
        for (int i = 0; i < LA; i++) {
            int idx = tid + i * 256;
            int row = idx / C4, c4 = idx % C4;
            float4 v = *(const float4*)(A + (size_t)(m0 + row) * K + kt + c4 * 4);
            As[c4 * 4 + 0][row] = v.x;
            As[c4 * 4 + 1][row] = v.y;
            As[c4 * 4 + 2][row] = v.z;
            As[c4 * 4 + 3][row] = v.w;
        }
        #pragma unroll
        for (int i = 0; i < LB; i++) {
            int idx = tid + i * 256;
            int row = idx / C4, c4 = idx % C4;
            int4 q4 = *(const int4*)(Q + (size_t)(n0 + row) * K + kt + c4 * 4);
            float s = S[(n0 + row) * NG + g];
            float z = Z[(n0 + row) * NG + g];
            Bs[c4 * 4 + 0][row] = ((float)q4.x - z) * s;
            Bs[c4 * 4 + 1][row] = ((float)q4.y - z) * s;
            Bs[c4 * 4 + 2][row] = ((float)q4.z - z) * s;
            Bs[c4 * 4 + 3][row] = ((float)q4.w - z) * s;
        }
        __syncthreads();

        #pragma unroll
        for (int k = 0; k < BK; k++) {
            float af[TM], bf[TN];
            #pragma unroll
            for (int i = 0; i < TM; i++) af[i] = As[k][ty * TM + i];
            #pragma unroll
            for (int j = 0; j < TN; j++) bf[j] = Bs[k][tx * TN + j];
            #pragma unroll
            for (int i = 0; i < TM; i++)
                #pragma unroll
                for (int j = 0; j < TN; j++)
                    acc[i][j] = fmaf(af[i], bf[j], acc[i][j]);
        }
        __syncthreads();
    }

    #pragma unroll
    for (int i = 0; i < TM; i++) {
        int m = m0 + ty * TM + i;
        #pragma unroll
        for (int j = 0; j < TN; j++) {
            int n = n0 + tx * TN + j;
            float v = acc[i][j] + bias[n];
            if (RELU) v = fmaxf(v, 0.0f);
            C[(size_t)m * N + n] = v;
        }
    }
}

extern "C" void kernel_launch(void* const* d_in, const int* in_sizes, int n_in,
                              void* d_out, int out_size)
{
    const float* x  = (const float*)d_in[0];
    const int*   q1 = (const int*)  d_in[1];
    const float* s1 = (const float*)d_in[2];
    const float* z1 = (const float*)d_in[3];
    const float* b1 = (const float*)d_in[4];
    const int*   q2 = (const int*)  d_in[5];
    const float* s2 = (const float*)d_in[6];
    const float* z2 = (const float*)d_in[7];
    const float* b2 = (const float*)d_in[8];
    float* out = (float*)d_out;

    float* h = nullptr;
    cudaGetSymbolAddress((void**)&h, g_h);   // no allocation; graph-safe

    // Layer 1: [512, 8192] = x @ w1^T, ReLU.  Grid 64x4 = 256 CTAs.
    dim3 g1(D_H / 128, B_DIM / 128);
    gemm_dq_kernel<128, 128, 16, 8, 8, true><<<g1, 256>>>(
        x, q1, s1, z1, b1, h, B_DIM, D_H, D_IN);

    // Layer 2: [512, 2048] = h @ w2^T.  Grid 32x8 = 256 CTAs (keeps chip full).
    dim3 g2(D_OUT / 64, B_DIM / 64);
    gemm_dq_kernel<64, 64, 16, 4, 4, false><<<g2, 256>>>(
        h, q2, s2, z2, b2, out, B_DIM, D_OUT, D_H);
}

// round 4
// speedup vs baseline: 6.1234x; 6.1234x over previous
#include <cuda_runtime.h>
#include <cuda_fp16.h>
#include <cstdint>

#define B_DIM 512
#define D_IN  2048
#define D_H   8192
#define D_OUT 2048

// fp16 copies: x (converted once) and hidden activation h.
__device__ __half g_x16[B_DIM * D_IN];
__device__ __half g_h[(size_t)B_DIM * D_H];

// ---------------- helpers ----------------
__device__ __forceinline__ uint32_t smem_u32(const void* p) {
    uint32_t a;
    asm("{ .reg .u64 t; cvta.to.shared.u64 t, %1; cvt.u32.u64 %0, t; }" : "=r"(a) : "l"(p));
    return a;
}
__device__ __forceinline__ void cp_async16(uint32_t dst, const void* src) {
    asm volatile("cp.async.cg.shared.global [%0], [%1], 16;" :: "r"(dst), "l"(src));
}
#define CP_COMMIT() asm volatile("cp.async.commit_group;" ::: "memory")
#define CP_WAIT0()  asm volatile("cp.async.wait_group 0;" ::: "memory")

__device__ __forceinline__ void ldsm4(uint32_t& r0, uint32_t& r1, uint32_t& r2, uint32_t& r3,
                                      uint32_t addr) {
    asm volatile("ldmatrix.sync.aligned.m8n8.x4.shared.b16 {%0,%1,%2,%3}, [%4];"
                 : "=r"(r0), "=r"(r1), "=r"(r2), "=r"(r3) : "r"(addr));
}
__device__ __forceinline__ void mma16816(float* c, const uint32_t* a, const uint32_t* b) {
    asm volatile("mma.sync.aligned.m16n8k16.row.col.f32.f16.f16.f32 "
                 "{%0,%1,%2,%3}, {%4,%5,%6,%7}, {%8,%9}, {%0,%1,%2,%3};"
                 : "+f"(c[0]), "+f"(c[1]), "+f"(c[2]), "+f"(c[3])
                 : "r"(a[0]), "r"(a[1]), "r"(a[2]), "r"(a[3]), "r"(b[0]), "r"(b[1]));
}

// x fp32 -> fp16
__global__ void cvt_x_kernel(const float* __restrict__ x, __half* __restrict__ o, int n) {
    int i = (blockIdx.x * blockDim.x + threadIdx.x) * 8;
    if (i < n) {
        float4 v0 = *(const float4*)(x + i);
        float4 v1 = *(const float4*)(x + i + 4);
        __half2 h0 = __floats2half2_rn(v0.x, v0.y), h1 = __floats2half2_rn(v0.z, v0.w);
        __half2 h2 = __floats2half2_rn(v1.x, v1.y), h3 = __floats2half2_rn(v1.z, v1.w);
        uint4 st;
        st.x = *(uint32_t*)&h0; st.y = *(uint32_t*)&h1;
        st.z = *(uint32_t*)&h2; st.w = *(uint32_t*)&h3;
        *(uint4*)(o + i) = st;
    }
}

// ---------------- fused INT4-dequant GEMM (HMMA) ----------------
// C[M,N] = A[M,K] @ dequant(Q[N,K])^T + bias, opt ReLU.
// BM=128, BK=64 (128B smem rows, XOR-swizzled). 256 threads.
template<int BN, int WM, int WN, bool IS_L1>
__global__ void __launch_bounds__(256)
gemm_i4(const __half* __restrict__ A, const int* __restrict__ Q,
        const float* __restrict__ S, const float* __restrict__ Z,
        const float* __restrict__ bias,
        float* __restrict__ outF, __half* __restrict__ outH,
        int N, int K)
{
    constexpr int BM = 128, BK = 64;
    constexpr int MI = WM / 16, NI = WN / 8;
    constexpr int NWN = BN / WN;               // warps along N
    constexpr int BCH = BN * 8 / 256;          // B 16B-chunks per thread

    const int tid = threadIdx.x, wid = tid >> 5, lane = tid & 31;
    const int wm = (wid / NWN) * WM, wn = (wid % NWN) * WN;
    const int m0 = blockIdx.y * BM, n0 = blockIdx.x * BN;
    const int NT = K / BK, NG = K >> 7;

    extern __shared__ char smem[];
    const uint32_t sA = smem_u32(smem);
    const uint32_t strA = BM * 128, strB = BN * 128;
    const uint32_t sB = sA + 2 * strA;
    char* const smB = smem + 2 * strA;

    float acc[MI][NI][4];
    #pragma unroll
    for (int mi = 0; mi < MI; mi++)
        #pragma unroll
        for (int ni = 0; ni < NI; ni++)
            #pragma unroll
            for (int j = 0; j < 4; j++) acc[mi][ni][j] = 0.0f;

    int4  qreg[BCH][2];
    float sreg[BCH], zreg[BCH];

    // ---- stage helpers ----
    auto prefetchA = [&](int it, int p) {
        const int kt = it * BK;
        #pragma unroll
        for (int i = 0; i < 4; i++) {
            int ch = tid + i * 256, row = ch >> 3, c = ch & 7;
            uint32_t dst = sA + p * strA + row * 128 + ((c ^ (row & 7)) << 4);
            cp_async16(dst, A + (size_t)(m0 + row) * K + kt + c * 8);
        }
    };
    auto prefetchB = [&](int it) {
        const int kt = it * BK, g = kt >> 7;
        #pragma unroll
        for (int i = 0; i < BCH; i++) {
            int ch = tid + i * 256, row = ch >> 3, c = ch & 7;
            const int* qp = Q + (size_t)(n0 + row) * K + kt + c * 8;
            qreg[i][0] = *(const int4*)qp;
            qreg[i][1] = *(const int4*)(qp + 4);
            sreg[i] = __ldg(S + (size_t)(n0 + row) * NG + g);
            zreg[i] = __ldg(Z + (size_t)(n0 + row) * NG + g);
        }
    };
    auto stsB = [&](int p) {
        #pragma unroll
        for (int i = 0; i < BCH; i++) {
            int ch = tid + i * 256, row = ch >> 3, c = ch & 7;
            float s = sreg[i], z = zreg[i];
            __half2 h0 = __floats2half2_rn(((float)qreg[i][0].x - z) * s, ((float)qreg[i][0].y - z) * s);
            __half2 h1 = __floats2half2_rn(((float)qreg[i][0].z - z) * s, ((float)qreg[i][0].w - z) * s);
            __half2 h2 = __floats2half2_rn(((float)qreg[i][1].x - z) * s, ((float)qreg[i][1].y - z) * s);
            __half2 h3 = __floats2half2_rn(((float)qreg[i][1].z - z) * s, ((float)qreg[i][1].w - z) * s);
            uint4 st;
            st.x = *(uint32_t*)&h0; st.y = *(uint32_t*)&h1;
            st.z = *(uint32_t*)&h2; st.w = *(uint32_t*)&h3;
            *(uint4*)(smB + p * strB + row * 128 + ((c ^ (row & 7)) << 4)) = st;
        }
    };
    auto compute = [&](int p) {
        const uint32_t baseA = sA + p * strA;
        const uint32_t baseB = sB + p * strB;
        const int arow = wm + (lane & 15);
        const int bg = lane >> 3, brin = lane & 7;
        #pragma unroll
        for (int ks = 0; ks < 4; ks++) {
            uint32_t a[MI][4], b[NI][2];
            const int ac = ks * 2 + (lane >> 4);
            #pragma unroll
            for (int mi = 0; mi < MI; mi++) {
                int r = arow + mi * 16;
                ldsm4(a[mi][0], a[mi][1], a[mi][2], a[mi][3],
                      baseA + r * 128 + ((ac ^ (r & 7)) << 4));
            }
            #pragma unroll
            for (int ni = 0; ni < NI; ni += 2) {
                int r = wn + ni * 8 + ((bg & 2) ? 8 : 0) + brin;
                int c = ks * 2 + (bg & 1);
                uint32_t b0, b1, b2, b3;
                ldsm4(b0, b1, b2, b3, baseB + r * 128 + ((c ^ (r & 7)) << 4));
                b[ni][0] = b0; b[ni][1] = b1; b[ni + 1][0] = b2; b[ni + 1][1] = b3;
            }
            #pragma unroll
            for (int mi = 0; mi < MI; mi++)
                #pragma unroll
                for (int ni = 0; ni < NI; ni++)
                    mma16816(acc[mi][ni], a[mi], b[ni]);
        }
    };

    // ---- pipeline ----
    prefetchB(0);
    prefetchA(0, 0);
    CP_COMMIT();
    stsB(0);
    CP_WAIT0();
    __syncthreads();

    for (int it = 0; it < NT; ++it) {
        const int p = it & 1;
        const bool more = (it + 1 < NT);
        if (more) {
            prefetchB(it + 1);          // LDG latency hides under compute
            prefetchA(it + 1, 1 - p);
            CP_COMMIT();
        }
        compute(p);
        if (more) {
            stsB(1 - p);
            CP_WAIT0();
        }
        __syncthreads();
    }

    // ---- epilogue: bias (+ReLU), store ----
    #pragma unroll
    for (int mi = 0; mi < MI; mi++) {
        const int r0 = m0 + wm + mi * 16 + (lane >> 2);
        const int r1 = r0 + 8;
        #pragma unroll
        for (int ni = 0; ni < NI; ni++) {
            const int col = n0 + wn + ni * 8 + ((lane & 3) * 2);
            const float b0v = __ldg(bias + col);
            const float b1v = __ldg(bias + col + 1);
            float v0 = acc[mi][ni][0] + b0v, v1 = acc[mi][ni][1] + b1v;
            float v2 = acc[mi][ni][2] + b0v, v3 = acc[mi][ni][3] + b1v;
            if (IS_L1) {
                __half2 p0 = __floats2half2_rn(fmaxf(v0, 0.0f), fmaxf(v1, 0.0f));
                __half2 p1 = __floats2half2_rn(fmaxf(v2, 0.0f), fmaxf(v3, 0.0f));
                *(__half2*)(outH + (size_t)r0 * N + col) = p0;
                *(__half2*)(outH + (size_t)r1 * N + col) = p1;
            } else {
                *(float2*)(outF + (size_t)r0 * N + col) = make_float2(v0, v1);
                *(float2*)(outF + (size_t)r1 * N + col) = make_float2(v2, v3);
            }
        }
    }
}

extern "C" void kernel_launch(void* const* d_in, const int* in_sizes, int n_in,
                              void* d_out, int out_size)
{
    const float* x  = (const float*)d_in[0];
    const int*   q1 = (const int*)  d_in[1];
    const float* s1 = (const float*)d_in[2];
    const float* z1 = (const float*)d_in[3];
    const float* b1 = (const float*)d_in[4];
    const int*   q2 = (const int*)  d_in[5];
    const float* s2 = (const float*)d_in[6];
    const float* z2 = (const float*)d_in[7];
    const float* b2 = (const float*)d_in[8];
    float* out = (float*)d_out;

    __half *x16 = nullptr, *h = nullptr;
    cudaGetSymbolAddress((void**)&x16, g_x16);
    cudaGetSymbolAddress((void**)&h,   g_h);

    constexpr int SMEM1 = 2 * 128 * 128 + 2 * 128 * 128;  // 64 KB
    constexpr int SMEM2 = 2 * 128 * 128 + 2 * 64 * 128;   // 48 KB
    cudaFuncSetAttribute(gemm_i4<128, 64, 32, true>,
                         cudaFuncAttributeMaxDynamicSharedMemorySize, SMEM1);
    cudaFuncSetAttribute(gemm_i4<64, 32, 32, false>,
                         cudaFuncAttributeMaxDynamicSharedMemorySize, SMEM2);

    // x -> fp16 (512*2048 = 1M elems, 8 per thread)
    cvt_x_kernel<<<(B_DIM * D_IN) / (256 * 8), 256>>>(x, x16, B_DIM * D_IN);

    // Layer 1: h = relu(x @ dq(q1)^T + b1)  [512, 8192]; grid 64x4
    dim3 g1(D_H / 128, B_DIM / 128);
    gemm_i4<128, 64, 32, true><<<g1, 256, SMEM1>>>(
        x16, q1, s1, z1, b1, nullptr, h, D_H, D_IN);

    // Layer 2: out = h @ dq(q2)^T + b2      [512, 2048]; grid 32x4
    dim3 g2(D_OUT / 64, B_DIM / 128);
    gemm_i4<64, 32, 32, false><<<g2, 256, SMEM2>>>(
        h, q2, s2, z2, b2, out, nullptr, D_OUT, D_H);
}

// round 5
// speedup vs baseline: 8.5933x; 1.4033x over previous
#include <cuda_runtime.h>
#include <cuda_fp16.h>
#include <cstdint>

#define B_DIM 512
#define D_IN  2048
#define D_H   8192
#define D_OUT 2048

// Scratch (static __device__ => allocation-rule safe)
__device__ __half g_x16[B_DIM * D_IN];                       // x in fp16
__device__ __half g_h[(size_t)B_DIM * D_H];                  // hidden fp16
__device__ __half g_w1h[(size_t)D_H * D_IN];                 // dequant w1 fp16
__device__ __half g_w2h[(size_t)D_OUT * D_H];                // dequant w2 fp16
__device__ float  g_part[2 * B_DIM * D_OUT];                 // split-K partials

// ---------------- helpers ----------------
__device__ __forceinline__ uint32_t smem_u32(const void* p) {
    uint32_t a;
    asm("{ .reg .u64 t; cvta.to.shared.u64 t, %1; cvt.u32.u64 %0, t; }" : "=r"(a) : "l"(p));
    return a;
}
__device__ __forceinline__ void cp_async16(uint32_t dst, const void* src) {
    asm volatile("cp.async.cg.shared.global [%0], [%1], 16;" :: "r"(dst), "l"(src));
}
#define CP_COMMIT() asm volatile("cp.async.commit_group;" ::: "memory")
#define CP_WAIT1()  asm volatile("cp.async.wait_group 1;" ::: "memory")

__device__ __forceinline__ void ldsm4(uint32_t& r0, uint32_t& r1, uint32_t& r2, uint32_t& r3,
                                      uint32_t addr) {
    asm volatile("ldmatrix.sync.aligned.m8n8.x4.shared.b16 {%0,%1,%2,%3}, [%4];"
                 : "=r"(r0), "=r"(r1), "=r"(r2), "=r"(r3) : "r"(addr));
}
__device__ __forceinline__ void mma16816(float* c, const uint32_t* a, const uint32_t* b) {
    asm volatile("mma.sync.aligned.m16n8k16.row.col.f32.f16.f16.f32 "
                 "{%0,%1,%2,%3}, {%4,%5,%6,%7}, {%8,%9}, {%0,%1,%2,%3};"
                 : "+f"(c[0]), "+f"(c[1]), "+f"(c[2]), "+f"(c[3])
                 : "r"(a[0]), "r"(a[1]), "r"(a[2]), "r"(a[3]), "r"(b[0]), "r"(b[1]));
}

// ---------------- pre-pass: INT4 dequant -> fp16 (both weights) ----------------
#define N1E (D_H * D_IN)          // 16.8M elems of w1
__global__ void __launch_bounds__(256)
dequant_w_kernel(const int* __restrict__ q1, const float* __restrict__ s1, const float* __restrict__ z1,
                 const int* __restrict__ q2, const float* __restrict__ s2, const float* __restrict__ z2,
                 __half* __restrict__ w1, __half* __restrict__ w2)
{
    const int gid = blockIdx.x * blockDim.x + threadIdx.x;
    long long e8 = (long long)gid * 8;

    const int* q; const float* S; const float* Z; __half* w; int K; long long e;
    if (e8 < N1E) { q = q1; S = s1; Z = z1; w = w1; K = D_IN; e = e8; }
    else          { q = q2; S = s2; Z = z2; w = w2; K = D_H;  e = e8 - N1E; }

    const int row = (int)(e / K), col = (int)(e % K);
    const int g = col >> 7, NG = K >> 7;
    const int4* qp = (const int4*)(q + e);
    int4 qa = qp[0], qb = qp[1];
    float s = __ldg(S + (size_t)row * NG + g);
    float z = __ldg(Z + (size_t)row * NG + g);

    __half2 h0 = __floats2half2_rn(((float)qa.x - z) * s, ((float)qa.y - z) * s);
    __half2 h1 = __floats2half2_rn(((float)qa.z - z) * s, ((float)qa.w - z) * s);
    __half2 h2 = __floats2half2_rn(((float)qb.x - z) * s, ((float)qb.y - z) * s);
    __half2 h3 = __floats2half2_rn(((float)qb.z - z) * s, ((float)qb.w - z) * s);
    uint4 st;
    st.x = *(uint32_t*)&h0; st.y = *(uint32_t*)&h1;
    st.z = *(uint32_t*)&h2; st.w = *(uint32_t*)&h3;
    *(uint4*)(w + e) = st;
}

// x fp32 -> fp16
__global__ void cvt_x_kernel(const float* __restrict__ x, __half* __restrict__ o, int n) {
    int i = (blockIdx.x * blockDim.x + threadIdx.x) * 8;
    if (i < n) {
        float4 v0 = *(const float4*)(x + i);
        float4 v1 = *(const float4*)(x + i + 4);
        __half2 h0 = __floats2half2_rn(v0.x, v0.y), h1 = __floats2half2_rn(v0.z, v0.w);
        __half2 h2 = __floats2half2_rn(v1.x, v1.y), h3 = __floats2half2_rn(v1.z, v1.w);
        uint4 st;
        st.x = *(uint32_t*)&h0; st.y = *(uint32_t*)&h1;
        st.z = *(uint32_t*)&h2; st.w = *(uint32_t*)&h3;
        *(uint4*)(o + i) = st;
    }
}

// split-K reduce + bias (layer 2 output)
__global__ void __launch_bounds__(256)
reduce_kernel(const float* __restrict__ part, const float* __restrict__ bias,
              float* __restrict__ out)
{
    int i = (blockIdx.x * blockDim.x + threadIdx.x) * 4;   // over 512*2048
    float4 p0 = *(const float4*)(part + i);
    float4 p1 = *(const float4*)(part + B_DIM * D_OUT + i);
    float4 bv = *(const float4*)(bias + (i & (D_OUT - 1)));
    float4 r;
    r.x = p0.x + p1.x + bv.x; r.y = p0.y + p1.y + bv.y;
    r.z = p0.z + p1.z + bv.z; r.w = p0.w + p1.w + bv.w;
    *(float4*)(out + i) = r;
}

// ---------------- clean fp16 GEMM, 3-stage cp.async ----------------
// C[M,N] = A[M,K] @ B[N,K]^T.  BM=128, BK=64 (128B rows, XOR swizzle), 256 thr.
// SPLIT: blockIdx.z selects K-half, writes fp32 partials (no bias).
// IS_L1: bias+ReLU, writes fp16.
template<int BN, int WM, int WN, bool IS_L1, bool SPLIT>
__global__ void __launch_bounds__(256)
gemm_f16(const __half* __restrict__ A, const __half* __restrict__ B,
         const float* __restrict__ bias,
         float* __restrict__ outF, __half* __restrict__ outH,
         int N, int K)
{
    constexpr int BM = 128, BK = 64, ST = 3;
    constexpr int MI = WM / 16, NI = WN / 8;
    constexpr int NWN = BN / WN;
    constexpr int ACH = BM * 8 / 256;          // A 16B-chunks per thread (4)
    constexpr int BCH = BN * 8 / 256;          // B 16B-chunks per thread

    const int tid = threadIdx.x, wid = tid >> 5, lane = tid & 31;
    const int wm = (wid / NWN) * WM, wn = (wid % NWN) * WN;
    const int m0 = blockIdx.y * BM, n0 = blockIdx.x * BN;

    const int KS  = SPLIT ? K / 2 : K;         // this CTA's K span
    const int kz0 = SPLIT ? blockIdx.z * KS : 0;
    const int NT  = KS / BK;

    extern __shared__ char smem[];
    const uint32_t sA = smem_u32(smem);
    const uint32_t strA = BM * 128, strB = BN * 128;
    const uint32_t sB = sA + ST * strA;

    float acc[MI][NI][4];
    #pragma unroll
    for (int mi = 0; mi < MI; mi++)
        #pragma unroll
        for (int ni = 0; ni < NI; ni++)
            #pragma unroll
            for (int j = 0; j < 4; j++) acc[mi][ni][j] = 0.0f;

    auto prefetch = [&](int it, int st) {
        const int kt = kz0 + it * BK;
        #pragma unroll
        for (int i = 0; i < ACH; i++) {
            int ch = tid + i * 256, row = ch >> 3, c = ch & 7;
            cp_async16(sA + st * strA + row * 128 + ((c ^ (row & 7)) << 4),
                       A + (size_t)(m0 + row) * K + kt + c * 8);
        }
        #pragma unroll
        for (int i = 0; i < BCH; i++) {
            int ch = tid + i * 256, row = ch >> 3, c = ch & 7;
            cp_async16(sB + st * strB + row * 128 + ((c ^ (row & 7)) << 4),
                       B + (size_t)(n0 + row) * K + kt + c * 8);
        }
        CP_COMMIT();
    };

    auto compute = [&](int st) {
        const uint32_t baseA = sA + st * strA;
        const uint32_t baseB = sB + st * strB;
        const int arow = wm + (lane & 15);
        const int bg = lane >> 3, brin = lane & 7;
        #pragma unroll
        for (int ks = 0; ks < 4; ks++) {
            uint32_t a[MI][4], b[NI][2];
            const int ac = ks * 2 + (lane >> 4);
            #pragma unroll
            for (int mi = 0; mi < MI; mi++) {
                int r = arow + mi * 16;
                ldsm4(a[mi][0], a[mi][1], a[mi][2], a[mi][3],
                      baseA + r * 128 + ((ac ^ (r & 7)) << 4));
            }
            #pragma unroll
            for (int ni = 0; ni < NI; ni += 2) {
                int r = wn + ni * 8 + ((bg & 2) ? 8 : 0) + brin;
                int c = ks * 2 + (bg & 1);
                uint32_t b0, b1, b2, b3;
                ldsm4(b0, b1, b2, b3, baseB + r * 128 + ((c ^ (r & 7)) << 4));
                b[ni][0] = b0; b[ni][1] = b1; b[ni + 1][0] = b2; b[ni + 1][1] = b3;
            }
            #pragma unroll
            for (int mi = 0; mi < MI; mi++)
                #pragma unroll
                for (int ni = 0; ni < NI; ni++)
                    mma16816(acc[mi][ni], a[mi], b[ni]);
        }
    };

    // prologue: fill 2 stages
    prefetch(0, 0);
    prefetch(1, 1);

    for (int it = 0; it < NT; ++it) {
        CP_WAIT1();                 // stage it%ST has landed
        __syncthreads();            // + everyone done computing stage (it-1)%ST
        if (it + ST - 1 < NT) prefetch(it + ST - 1, (it + ST - 1) % ST);
        compute(it % ST);
    }

    // ---- epilogue ----
    #pragma unroll
    for (int mi = 0; mi < MI; mi++) {
        const int r0 = m0 + wm + mi * 16 + (lane >> 2);
        const int r1 = r0 + 8;
        #pragma unroll
        for (int ni = 0; ni < NI; ni++) {
            const int col = n0 + wn + ni * 8 + ((lane & 3) * 2);
            if (IS_L1) {
                const float b0v = __ldg(bias + col), b1v = __ldg(bias + col + 1);
                __half2 p0 = __floats2half2_rn(fmaxf(acc[mi][ni][0] + b0v, 0.0f),
                                               fmaxf(acc[mi][ni][1] + b1v, 0.0f));
                __half2 p1 = __floats2half2_rn(fmaxf(acc[mi][ni][2] + b0v, 0.0f),
                                               fmaxf(acc[mi][ni][3] + b1v, 0.0f));
                *(__half2*)(outH + (size_t)r0 * N + col) = p0;
                *(__half2*)(outH + (size_t)r1 * N + col) = p1;
            } else {
                float* o = outF + (SPLIT ? (size_t)blockIdx.z * B_DIM * D_OUT : 0);
                *(float2*)(o + (size_t)r0 * N + col) = make_float2(acc[mi][ni][0], acc[mi][ni][1]);
                *(float2*)(o + (size_t)r1 * N + col) = make_float2(acc[mi][ni][2], acc[mi][ni][3]);
            }
        }
    }
}

extern "C" void kernel_launch(void* const* d_in, const int* in_sizes, int n_in,
                              void* d_out, int out_size)
{
    const float* x  = (const float*)d_in[0];
    const int*   q1 = (const int*)  d_in[1];
    const float* s1 = (const float*)d_in[2];
    const float* z1 = (const float*)d_in[3];
    const float* b1 = (const float*)d_in[4];
    const int*   q2 = (const int*)  d_in[5];
    const float* s2 = (const float*)d_in[6];
    const float* z2 = (const float*)d_in[7];
    const float* b2 = (const float*)d_in[8];
    float* out = (float*)d_out;

    __half *x16, *h, *w1h, *w2h; float* part;
    cudaGetSymbolAddress((void**)&x16, g_x16);
    cudaGetSymbolAddress((void**)&h,   g_h);
    cudaGetSymbolAddress((void**)&w1h, g_w1h);
    cudaGetSymbolAddress((void**)&w2h, g_w2h);
    cudaGetSymbolAddress((void**)&part, g_part);

    constexpr int SMEM1 = 3 * 128 * 128 + 3 * 128 * 128;  // 96 KB
    constexpr int SMEM2 = 3 * 128 * 128 + 3 * 64 * 128;   // 72 KB
    cudaFuncSetAttribute(gemm_f16<128, 64, 32, true,  false>,
                         cudaFuncAttributeMaxDynamicSharedMemorySize, SMEM1);
    cudaFuncSetAttribute(gemm_f16<64,  32, 32, false, true>,
                         cudaFuncAttributeMaxDynamicSharedMemorySize, SMEM2);

    // pre-pass: dequant both weights (33.5M fp16 outs, 8/thread)
    dequant_w_kernel<<<(N1E + D_OUT * D_H) / (256 * 8), 256>>>(
        q1, s1, z1, q2, s2, z2, w1h, w2h);
    cvt_x_kernel<<<(B_DIM * D_IN) / (256 * 8), 256>>>(x, x16, B_DIM * D_IN);

    // Layer 1: h = relu(x @ w1^T + b1)   grid 64x4 = 256 CTAs
    dim3 g1(D_H / 128, B_DIM / 128);
    gemm_f16<128, 64, 32, true, false><<<g1, 256, SMEM1>>>(
        x16, w1h, b1, nullptr, h, D_H, D_IN);

    // Layer 2: split-K=2, fp32 partials    grid 32x4x2 = 256 CTAs
    dim3 g2(D_OUT / 64, B_DIM / 128, 2);
    gemm_f16<64, 32, 32, false, true><<<g2, 256, SMEM2>>>(
        h, w2h, nullptr, part, nullptr, D_OUT, D_H);

    // out = part0 + part1 + b2
    reduce_kernel<<<(B_DIM * D_OUT) / (256 * 4), 256>>>(part, b2, out);
}

// round 6
// speedup vs baseline: 8.8910x; 1.0346x over previous
#include <cuda_runtime.h>
#include <cuda_fp16.h>
#include <cstdint>

#define B_DIM 512
#define D_IN  2048
#define D_H   8192
#define D_OUT 2048
#define SPLITK 4

// Scratch (static __device__ => allocation-rule safe)
__device__ __half g_x16[B_DIM * D_IN];                       // x in fp16
__device__ __half g_h[(size_t)B_DIM * D_H];                  // hidden fp16
__device__ __half g_w1h[(size_t)D_H * D_IN];                 // dequant w1 fp16
__device__ __half g_w2h[(size_t)D_OUT * D_H];                // dequant w2 fp16
__device__ float  g_part[(size_t)SPLITK * B_DIM * D_OUT];    // split-K partials

// ---------------- helpers ----------------
__device__ __forceinline__ uint32_t smem_u32(const void* p) {
    uint32_t a;
    asm("{ .reg .u64 t; cvta.to.shared.u64 t, %1; cvt.u32.u64 %0, t; }" : "=r"(a) : "l"(p));
    return a;
}
__device__ __forceinline__ void cp_async16(uint32_t dst, const void* src) {
    asm volatile("cp.async.cg.shared.global [%0], [%1], 16;" :: "r"(dst), "l"(src));
}
#define CP_COMMIT() asm volatile("cp.async.commit_group;" ::: "memory")
#define CP_WAIT1()  asm volatile("cp.async.wait_group 1;" ::: "memory")
#define CP_WAIT0()  asm volatile("cp.async.wait_group 0;" ::: "memory")

__device__ __forceinline__ void ldsm4(uint32_t& r0, uint32_t& r1, uint32_t& r2, uint32_t& r3,
                                      uint32_t addr) {
    asm volatile("ldmatrix.sync.aligned.m8n8.x4.shared.b16 {%0,%1,%2,%3}, [%4];"
                 : "=r"(r0), "=r"(r1), "=r"(r2), "=r"(r3) : "r"(addr));
}
__device__ __forceinline__ void mma16816(float* c, const uint32_t* a, const uint32_t* b) {
    asm volatile("mma.sync.aligned.m16n8k16.row.col.f32.f16.f16.f32 "
                 "{%0,%1,%2,%3}, {%4,%5,%6,%7}, {%8,%9}, {%0,%1,%2,%3};"
                 : "+f"(c[0]), "+f"(c[1]), "+f"(c[2]), "+f"(c[3])
                 : "r"(a[0]), "r"(a[1]), "r"(a[2]), "r"(a[3]), "r"(b[0]), "r"(b[1]));
}

// ---------------- pre-pass: dequant w1,w2 + convert x, one grid ----------------
#define N1E (D_H * D_IN)
#define N2E (D_OUT * D_H)
#define NXE (B_DIM * D_IN)
__global__ void __launch_bounds__(256)
prep_kernel(const int* __restrict__ q1, const float* __restrict__ s1, const float* __restrict__ z1,
            const int* __restrict__ q2, const float* __restrict__ s2, const float* __restrict__ z2,
            const float* __restrict__ x,
            __half* __restrict__ w1, __half* __restrict__ w2, __half* __restrict__ x16)
{
    const long long e8 = (long long)(blockIdx.x * blockDim.x + threadIdx.x) * 8;

    if (e8 < (long long)N1E + N2E) {
        const int* q; const float* S; const float* Z; __half* w; int K; long long e;
        if (e8 < N1E) { q = q1; S = s1; Z = z1; w = w1; K = D_IN; e = e8; }
        else          { q = q2; S = s2; Z = z2; w = w2; K = D_H;  e = e8 - N1E; }
        const int row = (int)(e / K), col = (int)(e % K);
        const int g = col >> 7, NG = K >> 7;
        const int4* qp = (const int4*)(q + e);
        int4 qa = qp[0], qb = qp[1];
        float s = __ldg(S + (size_t)row * NG + g);
        float z = __ldg(Z + (size_t)row * NG + g);
        __half2 h0 = __floats2half2_rn(((float)qa.x - z) * s, ((float)qa.y - z) * s);
        __half2 h1 = __floats2half2_rn(((float)qa.z - z) * s, ((float)qa.w - z) * s);
        __half2 h2 = __floats2half2_rn(((float)qb.x - z) * s, ((float)qb.y - z) * s);
        __half2 h3 = __floats2half2_rn(((float)qb.z - z) * s, ((float)qb.w - z) * s);
        uint4 st;
        st.x = *(uint32_t*)&h0; st.y = *(uint32_t*)&h1;
        st.z = *(uint32_t*)&h2; st.w = *(uint32_t*)&h3;
        *(uint4*)(w + e) = st;
    } else {
        long long e = e8 - ((long long)N1E + N2E);
        if (e < NXE) {
            float4 v0 = *(const float4*)(x + e);
            float4 v1 = *(const float4*)(x + e + 4);
            __half2 h0 = __floats2half2_rn(v0.x, v0.y), h1 = __floats2half2_rn(v0.z, v0.w);
            __half2 h2 = __floats2half2_rn(v1.x, v1.y), h3 = __floats2half2_rn(v1.z, v1.w);
            uint4 st;
            st.x = *(uint32_t*)&h0; st.y = *(uint32_t*)&h1;
            st.z = *(uint32_t*)&h2; st.w = *(uint32_t*)&h3;
            *(uint4*)(x16 + e) = st;
        }
    }
}

// split-K reduce + bias (layer 2 output)
__global__ void __launch_bounds__(256)
reduce_kernel(const float* __restrict__ part, const float* __restrict__ bias,
              float* __restrict__ out)
{
    int i = (blockIdx.x * blockDim.x + threadIdx.x) * 4;
    float4 bv = *(const float4*)(bias + (i & (D_OUT - 1)));
    float4 r = make_float4(bv.x, bv.y, bv.z, bv.w);
    #pragma unroll
    for (int k = 0; k < SPLITK; k++) {
        float4 p = *(const float4*)(part + (size_t)k * B_DIM * D_OUT + i);
        r.x += p.x; r.y += p.y; r.z += p.z; r.w += p.w;
    }
    *(float4*)(out + i) = r;
}

// ---------------- fp16 GEMM: 128 threads, 64x64 warp tiles, 3-stage ----------------
// C[M,N] = A[M,K] @ B[N,K]^T.  BM=BN=128, BK=64 (128B rows, XOR swizzle).
template<bool IS_L1, bool SPLIT>
__global__ void __launch_bounds__(128)
gemm_f16(const __half* __restrict__ A, const __half* __restrict__ B,
         const float* __restrict__ bias,
         float* __restrict__ outF, __half* __restrict__ outH,
         int N, int K)
{
    constexpr int BM = 128, BN = 128, BK = 64, ST = 3;
    constexpr int MI = 4, NI = 8;              // 64x64 per warp
    constexpr int ACH = BM * 8 / 128;          // 8 chunks/thread
    constexpr int BCH = BN * 8 / 128;          // 8

    const int tid = threadIdx.x, wid = tid >> 5, lane = tid & 31;
    const int wm = (wid >> 1) * 64, wn = (wid & 1) * 64;
    const int m0 = blockIdx.y * BM, n0 = blockIdx.x * BN;

    const int KS  = SPLIT ? K / SPLITK : K;
    const int kz0 = SPLIT ? blockIdx.z * KS : 0;
    const int NT  = KS / BK;

    extern __shared__ char smem[];
    const uint32_t sA = smem_u32(smem);
    const uint32_t strA = BM * 128, strB = BN * 128;
    const uint32_t sB = sA + ST * strA;

    float acc[MI][NI][4];
    #pragma unroll
    for (int mi = 0; mi < MI; mi++)
        #pragma unroll
        for (int ni = 0; ni < NI; ni++)
            #pragma unroll
            for (int j = 0; j < 4; j++) acc[mi][ni][j] = 0.0f;

    auto prefetch = [&](int it, int st) {
        const int kt = kz0 + it * BK;
        #pragma unroll
        for (int i = 0; i < ACH; i++) {
            int ch = tid + i * 128, row = ch >> 3, c = ch & 7;
            cp_async16(sA + st * strA + row * 128 + ((c ^ (row & 7)) << 4),
                       A + (size_t)(m0 + row) * K + kt + c * 8);
        }
        #pragma unroll
        for (int i = 0; i < BCH; i++) {
            int ch = tid + i * 128, row = ch >> 3, c = ch & 7;
            cp_async16(sB + st * strB + row * 128 + ((c ^ (row & 7)) << 4),
                       B + (size_t)(n0 + row) * K + kt + c * 8);
        }
        CP_COMMIT();
    };

    auto compute = [&](int st) {
        const uint32_t baseA = sA + st * strA;
        const uint32_t baseB = sB + st * strB;
        const int arow = wm + (lane & 15);
        const int bg = lane >> 3, brin = lane & 7;
        #pragma unroll
        for (int ks = 0; ks < 4; ks++) {
            uint32_t a[MI][4], b[NI][2];
            const int ac = ks * 2 + (lane >> 4);
            #pragma unroll
            for (int mi = 0; mi < MI; mi++) {
                int r = arow + mi * 16;
                ldsm4(a[mi][0], a[mi][1], a[mi][2], a[mi][3],
                      baseA + r * 128 + ((ac ^ (r & 7)) << 4));
            }
            #pragma unroll
            for (int ni = 0; ni < NI; ni += 2) {
                int r = wn + ni * 8 + ((bg & 2) ? 8 : 0) + brin;
                int c = ks * 2 + (bg & 1);
                uint32_t b0, b1, b2, b3;
                ldsm4(b0, b1, b2, b3, baseB + r * 128 + ((c ^ (r & 7)) << 4));
                b[ni][0] = b0; b[ni][1] = b1; b[ni + 1][0] = b2; b[ni + 1][1] = b3;
            }
            #pragma unroll
            for (int mi = 0; mi < MI; mi++)
                #pragma unroll
                for (int ni = 0; ni < NI; ni++)
                    mma16816(acc[mi][ni], a[mi], b[ni]);
        }
    };

    prefetch(0, 0);
    prefetch(1, 1);

    for (int it = 0; it < NT; ++it) {
        if (it == NT - 1) CP_WAIT0();   // tail: force last tile landed (no race)
        else              CP_WAIT1();
        __syncthreads();
        if (it + ST - 1 < NT) prefetch(it + ST - 1, (it + ST - 1) % ST);
        compute(it % ST);
    }

    // ---- epilogue ----
    #pragma unroll
    for (int mi = 0; mi < MI; mi++) {
        const int r0 = m0 + wm + mi * 16 + (lane >> 2);
        const int r1 = r0 + 8;
        #pragma unroll
        for (int ni = 0; ni < NI; ni++) {
            const int col = n0 + wn + ni * 8 + ((lane & 3) * 2);
            if (IS_L1) {
                const float b0v = __ldg(bias + col), b1v = __ldg(bias + col + 1);
                __half2 p0 = __floats2half2_rn(fmaxf(acc[mi][ni][0] + b0v, 0.0f),
                                               fmaxf(acc[mi][ni][1] + b1v, 0.0f));
                __half2 p1 = __floats2half2_rn(fmaxf(acc[mi][ni][2] + b0v, 0.0f),
                                               fmaxf(acc[mi][ni][3] + b1v, 0.0f));
                *(__half2*)(outH + (size_t)r0 * N + col) = p0;
                *(__half2*)(outH + (size_t)r1 * N + col) = p1;
            } else {
                float* o = outF + (SPLIT ? (size_t)blockIdx.z * B_DIM * D_OUT : 0);
                *(float2*)(o + (size_t)r0 * N + col) = make_float2(acc[mi][ni][0], acc[mi][ni][1]);
                *(float2*)(o + (size_t)r1 * N + col) = make_float2(acc[mi][ni][2], acc[mi][ni][3]);
            }
        }
    }
}

extern "C" void kernel_launch(void* const* d_in, const int* in_sizes, int n_in,
                              void* d_out, int out_size)
{
    const float* x  = (const float*)d_in[0];
    const int*   q1 = (const int*)  d_in[1];
    const float* s1 = (const float*)d_in[2];
    const float* z1 = (const float*)d_in[3];
    const float* b1 = (const float*)d_in[4];
    const int*   q2 = (const int*)  d_in[5];
    const float* s2 = (const float*)d_in[6];
    const float* z2 = (const float*)d_in[7];
    const float* b2 = (const float*)d_in[8];
    float* out = (float*)d_out;

    __half *x16, *h, *w1h, *w2h; float* part;
    cudaGetSymbolAddress((void**)&x16, g_x16);
    cudaGetSymbolAddress((void**)&h,   g_h);
    cudaGetSymbolAddress((void**)&w1h, g_w1h);
    cudaGetSymbolAddress((void**)&w2h, g_w2h);
    cudaGetSymbolAddress((void**)&part, g_part);

    constexpr int SMEM = 3 * 128 * 128 * 2;   // 96 KB
    cudaFuncSetAttribute(gemm_f16<true,  false>,
                         cudaFuncAttributeMaxDynamicSharedMemorySize, SMEM);
    cudaFuncSetAttribute(gemm_f16<false, true>,
                         cudaFuncAttributeMaxDynamicSharedMemorySize, SMEM);

    // pre-pass: dequant w1,w2 + x->fp16 in one grid
    {
        long long tot = (long long)N1E + N2E + NXE;
        int blocks = (int)((tot / 8 + 255) / 256);
        prep_kernel<<<blocks, 256>>>(q1, s1, z1, q2, s2, z2, x, w1h, w2h, x16);
    }

    // Layer 1: h = relu(x @ w1^T + b1)   grid 64x4 = 256 CTAs
    dim3 g1(D_H / 128, B_DIM / 128);
    gemm_f16<true, false><<<g1, 128, SMEM>>>(x16, w1h, b1, nullptr, h, D_H, D_IN);

    // Layer 2: split-K=4, fp32 partials   grid 16x4x4 = 256 CTAs
    dim3 g2(D_OUT / 128, B_DIM / 128, SPLITK);
    gemm_f16<false, true><<<g2, 128, SMEM>>>(h, w2h, nullptr, part, nullptr, D_OUT, D_H);

    // out = sum(partials) + b2
    reduce_kernel<<<(B_DIM * D_OUT) / (256 * 4), 256>>>(part, b2, out);
}